// round 2
// baseline (speedup 1.0000x reference)
#include <cuda_runtime.h>

#define HID    128
#define INPUT  24
#define SLOTS  16
#define TSTEPS 128
#define BATCH  2048

// ---------------- weight scratch (device globals; no allocation) ----------------
// Layout: [j][h][gate] quads so the inner loop does ONE LDG.128 per K-element.
__device__ float g_Wq0h[HID * HID * 4];     // layer0 recurrent:  W_hh0
__device__ float g_Wq0x[INPUT * HID * 4];   // layer0 input:      W_ih0
__device__ float g_Wq1x[HID * HID * 4];     // layer1 input:      W_ih1
__device__ float g_Wq1h[HID * HID * 4];     // layer1 recurrent:  W_hh1
__device__ float g_B0[HID * 4];             // b_ih0 + b_hh0, gate-quad per h
__device__ float g_B1[HID * 4];

__global__ void prep_kernel(const float* __restrict__ Wih0, const float* __restrict__ Whh0,
                            const float* __restrict__ bih0, const float* __restrict__ bhh0,
                            const float* __restrict__ Wih1, const float* __restrict__ Whh1,
                            const float* __restrict__ bih1, const float* __restrict__ bhh1) {
    int idx = blockIdx.x * blockDim.x + threadIdx.x;
    const int NHH = HID * HID;
    const int NIX = INPUT * HID;
    if (idx < NHH) {
        int j = idx / HID, h = idx % HID;
#pragma unroll
        for (int g = 0; g < 4; g++) g_Wq0h[(j * HID + h) * 4 + g] = Whh0[(g * HID + h) * HID + j];
        return;
    }
    idx -= NHH;
    if (idx < NIX) {
        int j = idx / HID, h = idx % HID;
#pragma unroll
        for (int g = 0; g < 4; g++) g_Wq0x[(j * HID + h) * 4 + g] = Wih0[(g * HID + h) * INPUT + j];
        return;
    }
    idx -= NIX;
    if (idx < NHH) {
        int j = idx / HID, h = idx % HID;
#pragma unroll
        for (int g = 0; g < 4; g++) g_Wq1x[(j * HID + h) * 4 + g] = Wih1[(g * HID + h) * HID + j];
        return;
    }
    idx -= NHH;
    if (idx < NHH) {
        int j = idx / HID, h = idx % HID;
#pragma unroll
        for (int g = 0; g < 4; g++) g_Wq1h[(j * HID + h) * 4 + g] = Whh1[(g * HID + h) * HID + j];
        return;
    }
    idx -= NHH;
    if (idx < HID) {
        int h = idx;
#pragma unroll
        for (int g = 0; g < 4; g++) g_B0[h * 4 + g] = bih0[g * HID + h] + bhh0[g * HID + h];
        return;
    }
    idx -= HID;
    if (idx < HID) {
        int h = idx;
#pragma unroll
        for (int g = 0; g < 4; g++) g_B1[h * 4 + g] = bih1[g * HID + h] + bhh1[g * HID + h];
    }
}

// ---------------- packed f32x2 helpers (Blackwell) ----------------
__device__ __forceinline__ unsigned long long pack_dup(float w) {
    unsigned long long r;
    unsigned u = __float_as_uint(w);
    asm("mov.b64 %0, {%1, %1};" : "=l"(r) : "r"(u));
    return r;
}
__device__ __forceinline__ unsigned long long fma2(unsigned long long a, unsigned long long b,
                                                   unsigned long long c) {
    unsigned long long d;
    asm("fma.rn.f32x2 %0, %1, %2, %3;" : "=l"(d) : "l"(a), "l"(b), "l"(c));
    return d;
}
__device__ __forceinline__ void unpack2(unsigned long long v, float& lo, float& hi) {
    unsigned a, b;
    asm("mov.b64 {%0, %1}, %2;" : "=r"(a), "=r"(b) : "l"(v));
    lo = __uint_as_float(a);
    hi = __uint_as_float(b);
}
__device__ __forceinline__ float sigf(float v) {
    return __fdividef(1.f, 1.f + __expf(-v));
}
__device__ __forceinline__ float tanhf_fast(float v) {
    return __fdividef(2.f, 1.f + __expf(-2.f * v)) - 1.f;
}

// One K-element: 1 LDG.128 (gate-quad weights) + 1 LDS.128 (4 batch slots) + 8 FFMA2
#define STEP_K(WPTR, KIDX, SBUF)                                                         \
    do {                                                                                 \
        float4 w4 = (WPTR)[(KIDX) * HID + h];                                            \
        ulonglong2 hv = *(const ulonglong2*)&SBUF[(KIDX)][q4];                           \
        unsigned long long wd;                                                           \
        wd = pack_dup(w4.x);                                                             \
        acc[0][0] = fma2(hv.x, wd, acc[0][0]);                                           \
        acc[0][1] = fma2(hv.y, wd, acc[0][1]);                                           \
        wd = pack_dup(w4.y);                                                             \
        acc[1][0] = fma2(hv.x, wd, acc[1][0]);                                           \
        acc[1][1] = fma2(hv.y, wd, acc[1][1]);                                           \
        wd = pack_dup(w4.z);                                                             \
        acc[2][0] = fma2(hv.x, wd, acc[2][0]);                                           \
        acc[2][1] = fma2(hv.y, wd, acc[2][1]);                                           \
        wd = pack_dup(w4.w);                                                             \
        acc[3][0] = fma2(hv.x, wd, acc[3][0]);                                           \
        acc[3][1] = fma2(hv.y, wd, acc[3][1]);                                           \
    } while (0)

__global__ __launch_bounds__(512, 1) void lstm_kernel(const float* __restrict__ x,
                                                      const float* __restrict__ Wfc,
                                                      const float* __restrict__ bfc,
                                                      float* __restrict__ out) {
    __shared__ __align__(16) float h0_s[HID][SLOTS];   // layer0 h state == layer1 input
    __shared__ __align__(16) float h2_s[HID][SLOTS];   // layer1 h state
    __shared__ __align__(16) float x_s[INPUT][SLOTS];  // current timestep input

    const int tid = threadIdx.x;
    const int h = tid >> 2;        // hidden unit owned by this thread
    const int q = tid & 3;         // batch-slot quarter
    const int q4 = q * 4;
    const int b0 = blockIdx.x * SLOTS;

    for (int i = tid; i < HID * SLOTS; i += 512) {
        (&h0_s[0][0])[i] = 0.f;
        (&h2_s[0][0])[i] = 0.f;
    }
    float c0[4] = {0.f, 0.f, 0.f, 0.f};
    float c1[4] = {0.f, 0.f, 0.f, 0.f};

    const float4* W0h = (const float4*)g_Wq0h;
    const float4* W0x = (const float4*)g_Wq0x;
    const float4* W1x = (const float4*)g_Wq1x;
    const float4* W1h = (const float4*)g_Wq1h;
    const float4 B0 = ((const float4*)g_B0)[h];
    const float4 B1 = ((const float4*)g_B1)[h];
    const unsigned long long b0d[4] = {pack_dup(B0.x), pack_dup(B0.y), pack_dup(B0.z), pack_dup(B0.w)};
    const unsigned long long b1d[4] = {pack_dup(B1.x), pack_dup(B1.y), pack_dup(B1.z), pack_dup(B1.w)};
    __syncthreads();

    for (int t = 0; t < TSTEPS; t++) {
        // stage x[:, t, :] for this CTA's 16 batch rows
        for (int i = tid; i < INPUT * SLOTS; i += 512) {
            int k = i >> 4;
            int s = i & (SLOTS - 1);
            x_s[k][s] = x[(b0 + s) * (TSTEPS * INPUT) + t * INPUT + k];
        }
        __syncthreads();  // S1: x staged, prev h2 writes visible

        // ---- layer 0 gates: W_hh0 @ h0 + W_ih0 @ x + bias ----
        unsigned long long acc[4][2];
#pragma unroll
        for (int g = 0; g < 4; g++) { acc[g][0] = b0d[g]; acc[g][1] = b0d[g]; }
#pragma unroll 4
        for (int j = 0; j < HID; j++) STEP_K(W0h, j, h0_s);
#pragma unroll 4
        for (int k = 0; k < INPUT; k++) STEP_K(W0x, k, x_s);
        __syncthreads();  // S2: all layer0 reads of h0_s done

        // ---- layer 0 cell update (thread-local: owns all 4 gates of (h, 4 slots)) ----
        {
            float ga[4][4];
#pragma unroll
            for (int g = 0; g < 4; g++) {
                unpack2(acc[g][0], ga[g][0], ga[g][1]);
                unpack2(acc[g][1], ga[g][2], ga[g][3]);
            }
            float hv4[4];
#pragma unroll
            for (int s = 0; s < 4; s++) {
                float iv = sigf(ga[0][s]);
                float fv = sigf(ga[1][s]);
                float gv = tanhf_fast(ga[2][s]);
                float ov = sigf(ga[3][s]);
                c0[s] = fv * c0[s] + iv * gv;
                hv4[s] = ov * tanhf_fast(c0[s]);
            }
            *(float4*)&h0_s[h][q4] = make_float4(hv4[0], hv4[1], hv4[2], hv4[3]);
        }
        __syncthreads();  // S3: new h1 (in h0_s) visible

        // ---- layer 1 gates: W_ih1 @ h1 + W_hh1 @ h2 + bias ----
#pragma unroll
        for (int g = 0; g < 4; g++) { acc[g][0] = b1d[g]; acc[g][1] = b1d[g]; }
#pragma unroll 4
        for (int j = 0; j < HID; j++) STEP_K(W1x, j, h0_s);
#pragma unroll 4
        for (int j = 0; j < HID; j++) STEP_K(W1h, j, h2_s);
        __syncthreads();  // S4: all layer1 reads of h2_s done

        // ---- layer 1 cell update ----
        {
            float ga[4][4];
#pragma unroll
            for (int g = 0; g < 4; g++) {
                unpack2(acc[g][0], ga[g][0], ga[g][1]);
                unpack2(acc[g][1], ga[g][2], ga[g][3]);
            }
            float hv4[4];
#pragma unroll
            for (int s = 0; s < 4; s++) {
                float iv = sigf(ga[0][s]);
                float fv = sigf(ga[1][s]);
                float gv = tanhf_fast(ga[2][s]);
                float ov = sigf(ga[3][s]);
                c1[s] = fv * c1[s] + iv * gv;
                hv4[s] = ov * tanhf_fast(c1[s]);
            }
            *(float4*)&h2_s[h][q4] = make_float4(hv4[0], hv4[1], hv4[2], hv4[3]);
        }
        __syncthreads();
    }

    // ---- final FC: out[b] = h2_last[b] . Wfc + bfc ----
    {
        int w = tid >> 5;  // one warp per batch slot (16 warps = 16 slots)
        int l = tid & 31;
        float s = 0.f;
#pragma unroll
        for (int j = l; j < HID; j += 32) s += h2_s[j][w] * Wfc[j];
#pragma unroll
        for (int o = 16; o > 0; o >>= 1) s += __shfl_down_sync(0xffffffffu, s, o);
        if (l == 0) out[b0 + w] = s + bfc[0];
    }
}

extern "C" void kernel_launch(void* const* d_in, const int* in_sizes, int n_in,
                              void* d_out, int out_size) {
    const float* x    = (const float*)d_in[0];
    const float* Wih0 = (const float*)d_in[1];
    const float* Whh0 = (const float*)d_in[2];
    const float* bih0 = (const float*)d_in[3];
    const float* bhh0 = (const float*)d_in[4];
    const float* Wih1 = (const float*)d_in[5];
    const float* Whh1 = (const float*)d_in[6];
    const float* bih1 = (const float*)d_in[7];
    const float* bhh1 = (const float*)d_in[8];
    const float* Wfc  = (const float*)d_in[9];
    const float* bfc  = (const float*)d_in[10];
    float* out = (float*)d_out;

    const int prep_total = HID * HID * 3 + INPUT * HID + HID * 2;
    prep_kernel<<<(prep_total + 255) / 256, 256>>>(Wih0, Whh0, bih0, bhh0, Wih1, Whh1, bih1, bhh1);
    lstm_kernel<<<BATCH / SLOTS, 512>>>(x, Wfc, bfc, out);
}

// round 3
// speedup vs baseline: 1.2117x; 1.2117x over previous
#include <cuda_runtime.h>

#define HID    128
#define INPUT  24
#define SLOTS  16
#define TSTEPS 128
#define BATCH  2048

// ---------------- weight scratch (device globals; no allocation) ----------------
// Layout: [j][h][gate] quads: one LDG.128 yields all 4 gate weights of (h, j).
__device__ float g_Wq0h[HID * HID * 4];     // layer0 recurrent:  W_hh0
__device__ float g_Wq0x[INPUT * HID * 4];   // layer0 input:      W_ih0
__device__ float g_Wq1x[HID * HID * 4];     // layer1 input:      W_ih1
__device__ float g_Wq1h[HID * HID * 4];     // layer1 recurrent:  W_hh1
__device__ float g_B0[HID * 4];             // b_ih0 + b_hh0, gate-quad per h
__device__ float g_B1[HID * 4];

__global__ void prep_kernel(const float* __restrict__ Wih0, const float* __restrict__ Whh0,
                            const float* __restrict__ bih0, const float* __restrict__ bhh0,
                            const float* __restrict__ Wih1, const float* __restrict__ Whh1,
                            const float* __restrict__ bih1, const float* __restrict__ bhh1) {
    int idx = blockIdx.x * blockDim.x + threadIdx.x;
    const int NHH = HID * HID;
    const int NIX = INPUT * HID;
    if (idx < NHH) {
        int j = idx / HID, h = idx % HID;
#pragma unroll
        for (int g = 0; g < 4; g++) g_Wq0h[(j * HID + h) * 4 + g] = Whh0[(g * HID + h) * HID + j];
        return;
    }
    idx -= NHH;
    if (idx < NIX) {
        int j = idx / HID, h = idx % HID;
#pragma unroll
        for (int g = 0; g < 4; g++) g_Wq0x[(j * HID + h) * 4 + g] = Wih0[(g * HID + h) * INPUT + j];
        return;
    }
    idx -= NIX;
    if (idx < NHH) {
        int j = idx / HID, h = idx % HID;
#pragma unroll
        for (int g = 0; g < 4; g++) g_Wq1x[(j * HID + h) * 4 + g] = Wih1[(g * HID + h) * HID + j];
        return;
    }
    idx -= NHH;
    if (idx < NHH) {
        int j = idx / HID, h = idx % HID;
#pragma unroll
        for (int g = 0; g < 4; g++) g_Wq1h[(j * HID + h) * 4 + g] = Whh1[(g * HID + h) * HID + j];
        return;
    }
    idx -= NHH;
    if (idx < HID) {
        int h = idx;
#pragma unroll
        for (int g = 0; g < 4; g++) g_B0[h * 4 + g] = bih0[g * HID + h] + bhh0[g * HID + h];
        return;
    }
    idx -= HID;
    if (idx < HID) {
        int h = idx;
#pragma unroll
        for (int g = 0; g < 4; g++) g_B1[h * 4 + g] = bih1[g * HID + h] + bhh1[g * HID + h];
    }
}

// ---------------- packed f32x2 helpers (Blackwell) ----------------
__device__ __forceinline__ unsigned long long pack_dup(float w) {
    unsigned long long r;
    unsigned u = __float_as_uint(w);
    asm("mov.b64 %0, {%1, %1};" : "=l"(r) : "r"(u));
    return r;
}
__device__ __forceinline__ unsigned long long fma2(unsigned long long a, unsigned long long b,
                                                   unsigned long long c) {
    unsigned long long d;
    asm("fma.rn.f32x2 %0, %1, %2, %3;" : "=l"(d) : "l"(a), "l"(b), "l"(c));
    return d;
}
__device__ __forceinline__ unsigned long long fadd2(unsigned long long a, unsigned long long b) {
    unsigned long long d;
    asm("add.rn.f32x2 %0, %1, %2;" : "=l"(d) : "l"(a), "l"(b));
    return d;
}
__device__ __forceinline__ void unpack2(unsigned long long v, float& lo, float& hi) {
    unsigned a, b;
    asm("mov.b64 {%0, %1}, %2;" : "=r"(a), "=r"(b) : "l"(v));
    lo = __uint_as_float(a);
    hi = __uint_as_float(b);
}
__device__ __forceinline__ float sigf(float v) {
    return __fdividef(1.f, 1.f + __expf(-v));
}
__device__ __forceinline__ float tanhf_fast(float v) {
    return __fdividef(2.f, 1.f + __expf(-2.f * v)) - 1.f;
}

// One K-element for 2 hidden units: 2 LDG.128 + 1 LDS.128 + 8 movs + 16 FFMA2
#define KSTEP(WP, J, SBUF)                                                                  \
    do {                                                                                    \
        float4 wA = (WP)[(J)*HID + hA];                                                     \
        float4 wB = (WP)[(J)*HID + hB];                                                     \
        ulonglong2 hv = *(const ulonglong2*)&SBUF[(J)][q4];                                 \
        unsigned long long wd;                                                              \
        wd = pack_dup(wA.x); acc[0][0][0] = fma2(hv.x, wd, acc[0][0][0]);                   \
                             acc[0][0][1] = fma2(hv.y, wd, acc[0][0][1]);                   \
        wd = pack_dup(wA.y); acc[1][0][0] = fma2(hv.x, wd, acc[1][0][0]);                   \
                             acc[1][0][1] = fma2(hv.y, wd, acc[1][0][1]);                   \
        wd = pack_dup(wA.z); acc[2][0][0] = fma2(hv.x, wd, acc[2][0][0]);                   \
                             acc[2][0][1] = fma2(hv.y, wd, acc[2][0][1]);                   \
        wd = pack_dup(wA.w); acc[3][0][0] = fma2(hv.x, wd, acc[3][0][0]);                   \
                             acc[3][0][1] = fma2(hv.y, wd, acc[3][0][1]);                   \
        wd = pack_dup(wB.x); acc[0][1][0] = fma2(hv.x, wd, acc[0][1][0]);                   \
                             acc[0][1][1] = fma2(hv.y, wd, acc[0][1][1]);                   \
        wd = pack_dup(wB.y); acc[1][1][0] = fma2(hv.x, wd, acc[1][1][0]);                   \
                             acc[1][1][1] = fma2(hv.y, wd, acc[1][1][1]);                   \
        wd = pack_dup(wB.z); acc[2][1][0] = fma2(hv.x, wd, acc[2][1][0]);                   \
                             acc[2][1][1] = fma2(hv.y, wd, acc[2][1][1]);                   \
        wd = pack_dup(wB.w); acc[3][1][0] = fma2(hv.x, wd, acc[3][1][0]);                   \
                             acc[3][1][1] = fma2(hv.y, wd, acc[3][1][1]);                   \
    } while (0)

__global__ __launch_bounds__(512, 1) void lstm_kernel(const float* __restrict__ x,
                                                      const float* __restrict__ Wfc,
                                                      const float* __restrict__ bfc,
                                                      float* __restrict__ out) {
    __shared__ __align__(16) float h0_s[HID][SLOTS];     // layer0 h == layer1 input (8 KB)
    __shared__ __align__(16) float h2_s[HID][SLOTS];     // layer1 h                 (8 KB)
    __shared__ __align__(16) float x_s[INPUT][SLOTS];    // current timestep input (1.5 KB)
    __shared__ __align__(16) ulonglong2 redT[4][256];    // K-split partial sums    (16 KB)

    const int tid = threadIdx.x;
    const int half = tid >> 8;     // 0: low-K half (+update), 1: high-K half
    const int r = tid & 255;
    const int hp = r >> 2;         // hidden pair index 0..63
    const int q = r & 3;           // slot quad index
    const int q4 = q * 4;
    const int hA = hp * 2;
    const int hB = hp * 2 + 1;
    const int b0 = blockIdx.x * SLOTS;

    for (int i = tid; i < HID * SLOTS; i += 512) {
        (&h0_s[0][0])[i] = 0.f;
        (&h2_s[0][0])[i] = 0.f;
    }
    float c0[2][4] = {{0.f, 0.f, 0.f, 0.f}, {0.f, 0.f, 0.f, 0.f}};
    float c1[2][4] = {{0.f, 0.f, 0.f, 0.f}, {0.f, 0.f, 0.f, 0.f}};

    const float4* W0h = (const float4*)g_Wq0h;
    const float4* W0x = (const float4*)g_Wq0x;
    const float4* W1x = (const float4*)g_Wq1x;
    const float4* W1h = (const float4*)g_Wq1h;
    const float4 B0a = ((const float4*)g_B0)[hA];
    const float4 B0b = ((const float4*)g_B0)[hB];
    const float4 B1a = ((const float4*)g_B1)[hA];
    const float4 B1b = ((const float4*)g_B1)[hB];
    __syncthreads();

    for (int t = 0; t < TSTEPS; t++) {
        // stage x[:, t, :] (coalesced-ish: consecutive tid -> consecutive k)
        for (int i = tid; i < INPUT * SLOTS; i += 512) {
            int s = i / INPUT;
            int k = i - s * INPUT;
            x_s[k][s] = x[(b0 + s) * (TSTEPS * INPUT) + t * INPUT + k];
        }
        __syncthreads();  // S0: x staged, prev h writes visible

        unsigned long long acc[4][2][2];

        // ================= layer 0 =================
        if (half == 0) {
            unsigned long long wd;
            wd = pack_dup(B0a.x); acc[0][0][0] = wd; acc[0][0][1] = wd;
            wd = pack_dup(B0a.y); acc[1][0][0] = wd; acc[1][0][1] = wd;
            wd = pack_dup(B0a.z); acc[2][0][0] = wd; acc[2][0][1] = wd;
            wd = pack_dup(B0a.w); acc[3][0][0] = wd; acc[3][0][1] = wd;
            wd = pack_dup(B0b.x); acc[0][1][0] = wd; acc[0][1][1] = wd;
            wd = pack_dup(B0b.y); acc[1][1][0] = wd; acc[1][1][1] = wd;
            wd = pack_dup(B0b.z); acc[2][1][0] = wd; acc[2][1][1] = wd;
            wd = pack_dup(B0b.w); acc[3][1][0] = wd; acc[3][1][1] = wd;
#pragma unroll 4
            for (int j = 0; j < 64; j++) KSTEP(W0h, j, h0_s);
#pragma unroll 4
            for (int k = 0; k < 12; k++) KSTEP(W0x, k, x_s);
        } else {
#pragma unroll
            for (int g = 0; g < 4; g++)
#pragma unroll
                for (int hh = 0; hh < 2; hh++) { acc[g][hh][0] = 0ull; acc[g][hh][1] = 0ull; }
#pragma unroll 4
            for (int j = 64; j < 128; j++) KSTEP(W0h, j, h0_s);
#pragma unroll 4
            for (int k = 12; k < 24; k++) KSTEP(W0x, k, x_s);
            // pass A: gates 0,1
            redT[0][r] = make_ulonglong2(acc[0][0][0], acc[0][0][1]);
            redT[1][r] = make_ulonglong2(acc[0][1][0], acc[0][1][1]);
            redT[2][r] = make_ulonglong2(acc[1][0][0], acc[1][0][1]);
            redT[3][r] = make_ulonglong2(acc[1][1][0], acc[1][1][1]);
        }
        __syncthreads();  // S1: pass A visible
        if (half == 0) {
            ulonglong2 v;
            v = redT[0][r]; acc[0][0][0] = fadd2(acc[0][0][0], v.x); acc[0][0][1] = fadd2(acc[0][0][1], v.y);
            v = redT[1][r]; acc[0][1][0] = fadd2(acc[0][1][0], v.x); acc[0][1][1] = fadd2(acc[0][1][1], v.y);
            v = redT[2][r]; acc[1][0][0] = fadd2(acc[1][0][0], v.x); acc[1][0][1] = fadd2(acc[1][0][1], v.y);
            v = redT[3][r]; acc[1][1][0] = fadd2(acc[1][1][0], v.x); acc[1][1][1] = fadd2(acc[1][1][1], v.y);
        }
        __syncthreads();  // S2: pass A consumed
        if (half == 1) {
            // pass B: gates 2,3
            redT[0][r] = make_ulonglong2(acc[2][0][0], acc[2][0][1]);
            redT[1][r] = make_ulonglong2(acc[2][1][0], acc[2][1][1]);
            redT[2][r] = make_ulonglong2(acc[3][0][0], acc[3][0][1]);
            redT[3][r] = make_ulonglong2(acc[3][1][0], acc[3][1][1]);
        }
        __syncthreads();  // S3: pass B visible
        if (half == 0) {
            ulonglong2 v;
            v = redT[0][r]; acc[2][0][0] = fadd2(acc[2][0][0], v.x); acc[2][0][1] = fadd2(acc[2][0][1], v.y);
            v = redT[1][r]; acc[2][1][0] = fadd2(acc[2][1][0], v.x); acc[2][1][1] = fadd2(acc[2][1][1], v.y);
            v = redT[2][r]; acc[3][0][0] = fadd2(acc[3][0][0], v.x); acc[3][0][1] = fadd2(acc[3][0][1], v.y);
            v = redT[3][r]; acc[3][1][0] = fadd2(acc[3][1][0], v.x); acc[3][1][1] = fadd2(acc[3][1][1], v.y);
            // cell update layer 0 (owns 2 hidden units x 4 slots)
#pragma unroll
            for (int hh = 0; hh < 2; hh++) {
                float g0[4], g1[4], g2[4], g3[4];
                unpack2(acc[0][hh][0], g0[0], g0[1]); unpack2(acc[0][hh][1], g0[2], g0[3]);
                unpack2(acc[1][hh][0], g1[0], g1[1]); unpack2(acc[1][hh][1], g1[2], g1[3]);
                unpack2(acc[2][hh][0], g2[0], g2[1]); unpack2(acc[2][hh][1], g2[2], g2[3]);
                unpack2(acc[3][hh][0], g3[0], g3[1]); unpack2(acc[3][hh][1], g3[2], g3[3]);
                float hv4[4];
#pragma unroll
                for (int s = 0; s < 4; s++) {
                    float iv = sigf(g0[s]);
                    float fv = sigf(g1[s]);
                    float gv = tanhf_fast(g2[s]);
                    float ov = sigf(g3[s]);
                    c0[hh][s] = fv * c0[hh][s] + iv * gv;
                    hv4[s] = ov * tanhf_fast(c0[hh][s]);
                }
                *(float4*)&h0_s[hh ? hB : hA][q4] = make_float4(hv4[0], hv4[1], hv4[2], hv4[3]);
            }
        }
        __syncthreads();  // S4: new h1 visible

        // ================= layer 1 =================
        if (half == 0) {
            unsigned long long wd;
            wd = pack_dup(B1a.x); acc[0][0][0] = wd; acc[0][0][1] = wd;
            wd = pack_dup(B1a.y); acc[1][0][0] = wd; acc[1][0][1] = wd;
            wd = pack_dup(B1a.z); acc[2][0][0] = wd; acc[2][0][1] = wd;
            wd = pack_dup(B1a.w); acc[3][0][0] = wd; acc[3][0][1] = wd;
            wd = pack_dup(B1b.x); acc[0][1][0] = wd; acc[0][1][1] = wd;
            wd = pack_dup(B1b.y); acc[1][1][0] = wd; acc[1][1][1] = wd;
            wd = pack_dup(B1b.z); acc[2][1][0] = wd; acc[2][1][1] = wd;
            wd = pack_dup(B1b.w); acc[3][1][0] = wd; acc[3][1][1] = wd;
#pragma unroll 4
            for (int j = 0; j < 64; j++) KSTEP(W1x, j, h0_s);
#pragma unroll 4
            for (int j = 0; j < 64; j++) KSTEP(W1h, j, h2_s);
        } else {
#pragma unroll
            for (int g = 0; g < 4; g++)
#pragma unroll
                for (int hh = 0; hh < 2; hh++) { acc[g][hh][0] = 0ull; acc[g][hh][1] = 0ull; }
#pragma unroll 4
            for (int j = 64; j < 128; j++) KSTEP(W1x, j, h0_s);
#pragma unroll 4
            for (int j = 64; j < 128; j++) KSTEP(W1h, j, h2_s);
            redT[0][r] = make_ulonglong2(acc[0][0][0], acc[0][0][1]);
            redT[1][r] = make_ulonglong2(acc[0][1][0], acc[0][1][1]);
            redT[2][r] = make_ulonglong2(acc[1][0][0], acc[1][0][1]);
            redT[3][r] = make_ulonglong2(acc[1][1][0], acc[1][1][1]);
        }
        __syncthreads();  // S1'
        if (half == 0) {
            ulonglong2 v;
            v = redT[0][r]; acc[0][0][0] = fadd2(acc[0][0][0], v.x); acc[0][0][1] = fadd2(acc[0][0][1], v.y);
            v = redT[1][r]; acc[0][1][0] = fadd2(acc[0][1][0], v.x); acc[0][1][1] = fadd2(acc[0][1][1], v.y);
            v = redT[2][r]; acc[1][0][0] = fadd2(acc[1][0][0], v.x); acc[1][0][1] = fadd2(acc[1][0][1], v.y);
            v = redT[3][r]; acc[1][1][0] = fadd2(acc[1][1][0], v.x); acc[1][1][1] = fadd2(acc[1][1][1], v.y);
        }
        __syncthreads();  // S2'
        if (half == 1) {
            redT[0][r] = make_ulonglong2(acc[2][0][0], acc[2][0][1]);
            redT[1][r] = make_ulonglong2(acc[2][1][0], acc[2][1][1]);
            redT[2][r] = make_ulonglong2(acc[3][0][0], acc[3][0][1]);
            redT[3][r] = make_ulonglong2(acc[3][1][0], acc[3][1][1]);
        }
        __syncthreads();  // S3'
        if (half == 0) {
            ulonglong2 v;
            v = redT[0][r]; acc[2][0][0] = fadd2(acc[2][0][0], v.x); acc[2][0][1] = fadd2(acc[2][0][1], v.y);
            v = redT[1][r]; acc[2][1][0] = fadd2(acc[2][1][0], v.x); acc[2][1][1] = fadd2(acc[2][1][1], v.y);
            v = redT[2][r]; acc[3][0][0] = fadd2(acc[3][0][0], v.x); acc[3][0][1] = fadd2(acc[3][0][1], v.y);
            v = redT[3][r]; acc[3][1][0] = fadd2(acc[3][1][0], v.x); acc[3][1][1] = fadd2(acc[3][1][1], v.y);
#pragma unroll
            for (int hh = 0; hh < 2; hh++) {
                float g0[4], g1[4], g2[4], g3[4];
                unpack2(acc[0][hh][0], g0[0], g0[1]); unpack2(acc[0][hh][1], g0[2], g0[3]);
                unpack2(acc[1][hh][0], g1[0], g1[1]); unpack2(acc[1][hh][1], g1[2], g1[3]);
                unpack2(acc[2][hh][0], g2[0], g2[1]); unpack2(acc[2][hh][1], g2[2], g2[3]);
                unpack2(acc[3][hh][0], g3[0], g3[1]); unpack2(acc[3][hh][1], g3[2], g3[3]);
                float hv4[4];
#pragma unroll
                for (int s = 0; s < 4; s++) {
                    float iv = sigf(g0[s]);
                    float fv = sigf(g1[s]);
                    float gv = tanhf_fast(g2[s]);
                    float ov = sigf(g3[s]);
                    c1[hh][s] = fv * c1[hh][s] + iv * gv;
                    hv4[s] = ov * tanhf_fast(c1[hh][s]);
                }
                *(float4*)&h2_s[hh ? hB : hA][q4] = make_float4(hv4[0], hv4[1], hv4[2], hv4[3]);
            }
        }
        __syncthreads();  // S4': new h2 visible (serves as next S0 precondition)
    }

    // ---- final FC: out[b] = h2_last[b] . Wfc + bfc ----
    {
        int w = tid >> 5;  // one warp per batch slot (16 warps = 16 slots)
        int l = tid & 31;
        float s = 0.f;
#pragma unroll
        for (int j = l; j < HID; j += 32) s += h2_s[j][w] * Wfc[j];
#pragma unroll
        for (int o = 16; o > 0; o >>= 1) s += __shfl_down_sync(0xffffffffu, s, o);
        if (l == 0) out[b0 + w] = s + bfc[0];
    }
}

extern "C" void kernel_launch(void* const* d_in, const int* in_sizes, int n_in,
                              void* d_out, int out_size) {
    const float* x    = (const float*)d_in[0];
    const float* Wih0 = (const float*)d_in[1];
    const float* Whh0 = (const float*)d_in[2];
    const float* bih0 = (const float*)d_in[3];
    const float* bhh0 = (const float*)d_in[4];
    const float* Wih1 = (const float*)d_in[5];
    const float* Whh1 = (const float*)d_in[6];
    const float* bih1 = (const float*)d_in[7];
    const float* bhh1 = (const float*)d_in[8];
    const float* Wfc  = (const float*)d_in[9];
    const float* bfc  = (const float*)d_in[10];
    float* out = (float*)d_out;

    const int prep_total = HID * HID * 3 + INPUT * HID + HID * 2;
    prep_kernel<<<(prep_total + 255) / 256, 256>>>(Wih0, Whh0, bih0, bhh0, Wih1, Whh1, bih1, bhh1);
    lstm_kernel<<<BATCH / SLOTS, 512>>>(x, Wfc, bfc, out);
}